// round 1
// baseline (speedup 1.0000x reference)
#include <cuda_runtime.h>

typedef unsigned long long u64;

#define B_    8
#define DIM_  1024
#define T_    4096
#define CB_   4096
#define CD_   8
#define BT_   (B_*T_)

static const size_t IDX_OFF_  = (size_t)B_ * DIM_ * T_;          // 33554432
static const size_t LOSS_OFF_ = (size_t)B_ * DIM_ * T_ + BT_;    // 33587200

// ---------------- device scratch (no allocations allowed) ----------------
__device__ float g_cn[CB_ * CD_];          // normalized codebook [j][c]
__device__ float g_Win[DIM_ * CD_];        // weight-normed in_proj, transposed [d][o]
__device__ float g_Wout2[DIM_ * 2 * CD_];  // weight-normed out_proj, splatted [o][c][2]
__device__ float g_bout2[DIM_ * 2];        // b_out splatted [o][2]
__device__ float g_ze[(size_t)BT_ * CD_];  // encodings z_e [t][c]  (1 MB)

// ---------------- f32x2 helpers (FFMA2 only reachable via PTX) ----------------
__device__ __forceinline__ u64 f2mul(u64 a, u64 b) {
    u64 r; asm("mul.rn.f32x2 %0, %1, %2;" : "=l"(r) : "l"(a), "l"(b)); return r;
}
__device__ __forceinline__ u64 f2fma(u64 a, u64 b, u64 c) {
    u64 r; asm("fma.rn.f32x2 %0, %1, %2, %3;" : "=l"(r) : "l"(a), "l"(b), "l"(c)); return r;
}
__device__ __forceinline__ float2 f2unpack(u64 a) {
    float x, y; asm("mov.b64 {%0, %1}, %2;" : "=f"(x), "=f"(y) : "l"(a));
    return make_float2(x, y);
}
__device__ __forceinline__ u64 f2pack(float x, float y) {
    u64 r; asm("mov.b64 %0, {%1, %2};" : "=l"(r) : "f"(x), "f"(y)); return r;
}

// ---------------- prep: weight-norm scales, normalized codebook, splats ----------------
__global__ void __launch_bounds__(256) prep_kernel(
    const float* __restrict__ v_in, const float* __restrict__ g_in,
    const float* __restrict__ codebook,
    const float* __restrict__ v_out, const float* __restrict__ g_out,
    const float* __restrict__ b_out, float* __restrict__ dout)
{
    const int r = blockIdx.x * 256 + threadIdx.x;
    if (r < CB_) {
        // normalize one codebook row (division to match reference exactly)
        float v[CD_]; float s = 0.f;
#pragma unroll
        for (int c = 0; c < CD_; ++c) { v[c] = codebook[(size_t)r * CD_ + c]; s += v[c] * v[c]; }
        float n = fmaxf(sqrtf(s), 1e-12f);
#pragma unroll
        for (int c = 0; c < CD_; ++c) g_cn[(size_t)r * CD_ + c] = v[c] / n;
    } else if (r < CB_ + DIM_) {
        // out_proj row: weight-norm scale, splat for f32x2
        const int o = r - CB_;
        float v[CD_]; float s = 0.f;
#pragma unroll
        for (int c = 0; c < CD_; ++c) { v[c] = v_out[(size_t)o * CD_ + c]; s += v[c] * v[c]; }
        float sc = g_out[o] / sqrtf(s);
#pragma unroll
        for (int c = 0; c < CD_; ++c) {
            float w = v[c] * sc;
            g_Wout2[o * 16 + 2 * c]     = w;
            g_Wout2[o * 16 + 2 * c + 1] = w;
        }
        float bb = b_out[o];
        g_bout2[o * 2] = bb; g_bout2[o * 2 + 1] = bb;
    } else if (r < CB_ + DIM_ + CD_ * 32) {
        // in_proj: one warp per output channel reduces ||v_in[o,:]||, then fills transposed W_in
        const int idx  = r - (CB_ + DIM_);
        const int w    = idx >> 5;
        const int lane = idx & 31;
        float s = 0.f;
        for (int d = lane; d < DIM_; d += 32) {
            float v = v_in[(size_t)w * DIM_ + d]; s += v * v;
        }
#pragma unroll
        for (int off = 16; off > 0; off >>= 1) s += __shfl_xor_sync(0xffffffffu, s, off);
        float sc = g_in[w] / sqrtf(s);
        for (int d = lane; d < DIM_; d += 32)
            g_Win[d * CD_ + w] = v_in[(size_t)w * DIM_ + d] * sc;
    } else if (r < CB_ + DIM_ + CD_ * 32 + B_) {
        // zero loss accumulators every launch (graph-replay safe; d_out is poisoned)
        dout[LOSS_OFF_ + (r - (CB_ + DIM_ + CD_ * 32))] = 0.f;
    }
}

// ---------------- K1: z_e = W_in @ z + b_in   (memory-bound: 128 MB read) ----------------
__global__ void __launch_bounds__(256) ze_kernel(const float* __restrict__ z,
                                                 const float* __restrict__ b_in)
{
    const int t  = blockIdx.x * 256 + threadIdx.x;   // global timestep over B*T
    const int b  = t >> 12;
    const int tl = t & (T_ - 1);
    const float* zp = z + (size_t)b * DIM_ * T_ + tl;

    float a0 = b_in[0], a1 = b_in[1], a2 = b_in[2], a3 = b_in[3];
    float a4 = b_in[4], a5 = b_in[5], a6 = b_in[6], a7 = b_in[7];

#pragma unroll 8
    for (int d = 0; d < DIM_; ++d) {
        float zv = __ldg(zp + (size_t)d * T_);       // coalesced 128B/warp
        float4 w0 = *(const float4*)(g_Win + d * CD_);      // uniform -> L1 broadcast
        float4 w1 = *(const float4*)(g_Win + d * CD_ + 4);
        a0 = fmaf(w0.x, zv, a0); a1 = fmaf(w0.y, zv, a1);
        a2 = fmaf(w0.z, zv, a2); a3 = fmaf(w0.w, zv, a3);
        a4 = fmaf(w1.x, zv, a4); a5 = fmaf(w1.y, zv, a5);
        a6 = fmaf(w1.z, zv, a6); a7 = fmaf(w1.w, zv, a7);
    }
    float4* o = (float4*)(g_ze + (size_t)t * CD_);
    o[0] = make_float4(a0, a1, a2, a3);
    o[1] = make_float4(a4, a5, a6, a7);
}

// ---------------- K2: argmax search + loss + out-proj (fma-bound + 128 MB write) ----------------
__global__ void __launch_bounds__(128) vq_kernel(const float* __restrict__ codebook,
                                                 float* __restrict__ dout)
{
    const int p  = blockIdx.x * 128 + threadIdx.x;   // pair of adjacent timesteps
    const int t0 = p << 1;
    const int b  = t0 >> 12;
    const int tl = t0 & (T_ - 1);

    // load z_e for both timesteps as f32x2 pairs
    const ulonglong2* zr = (const ulonglong2*)(g_ze + (size_t)t0 * CD_);
    ulonglong2 zA = zr[0], zB = zr[1];   // t0: (e0,e1)(e2,e3) | (e4,e5)(e6,e7)
    ulonglong2 zC = zr[2], zD = zr[3];   // t1

    float best_a = -3.4e38f, best_b = -3.4e38f;
    int ia = 0, ib = 0;

#pragma unroll 4
    for (int j = 0; j < CB_; ++j) {
        const ulonglong2* cr = (const ulonglong2*)(g_cn + (size_t)j * CD_);
        ulonglong2 c0 = cr[0], c1 = cr[1];           // uniform -> L1 broadcast hit

        u64 da = f2mul(zA.x, c0.x);
        da = f2fma(zA.y, c0.y, da);
        da = f2fma(zB.x, c1.x, da);
        da = f2fma(zB.y, c1.y, da);
        u64 db = f2mul(zC.x, c0.x);
        db = f2fma(zC.y, c0.y, db);
        db = f2fma(zD.x, c1.x, db);
        db = f2fma(zD.y, c1.y, db);

        float2 fa = f2unpack(da), fb = f2unpack(db);
        float dota = fa.x + fa.y;
        float dotb = fb.x + fb.y;
        if (dota > best_a) { best_a = dota; ia = j; }   // strict > == first-min tie-break
        if (dotb > best_b) { best_b = dotb; ib = j; }
    }

    // indices (as float values — exactly representable)
    dout[IDX_OFF_ + t0]     = (float)ia;
    dout[IDX_OFF_ + t0 + 1] = (float)ib;

    // gather UN-normalized codes
    float4 qa0 = __ldg((const float4*)(codebook + (size_t)ia * CD_));
    float4 qa1 = __ldg((const float4*)(codebook + (size_t)ia * CD_) + 1);
    float4 qb0 = __ldg((const float4*)(codebook + (size_t)ib * CD_));
    float4 qb1 = __ldg((const float4*)(codebook + (size_t)ib * CD_) + 1);

    // loss partial: sum (z_e - z_q)^2 over both timesteps
    const float4* er = (const float4*)(g_ze + (size_t)t0 * CD_);
    float4 ea0 = er[0], ea1 = er[1], eb0 = er[2], eb1 = er[3];
    float l = 0.f, d_;
    d_ = ea0.x - qa0.x; l += d_ * d_;  d_ = ea0.y - qa0.y; l += d_ * d_;
    d_ = ea0.z - qa0.z; l += d_ * d_;  d_ = ea0.w - qa0.w; l += d_ * d_;
    d_ = ea1.x - qa1.x; l += d_ * d_;  d_ = ea1.y - qa1.y; l += d_ * d_;
    d_ = ea1.z - qa1.z; l += d_ * d_;  d_ = ea1.w - qa1.w; l += d_ * d_;
    d_ = eb0.x - qb0.x; l += d_ * d_;  d_ = eb0.y - qb0.y; l += d_ * d_;
    d_ = eb0.z - qb0.z; l += d_ * d_;  d_ = eb0.w - qb0.w; l += d_ * d_;
    d_ = eb1.x - qb1.x; l += d_ * d_;  d_ = eb1.y - qb1.y; l += d_ * d_;
    d_ = eb1.z - qb1.z; l += d_ * d_;  d_ = eb1.w - qb1.w; l += d_ * d_;

    __shared__ float sl[128];
    sl[threadIdx.x] = l;
    __syncthreads();
#pragma unroll
    for (int s = 64; s > 0; s >>= 1) {
        if (threadIdx.x < s) sl[threadIdx.x] += sl[threadIdx.x + s];
        __syncthreads();
    }
    if (threadIdx.x == 0)
        atomicAdd(&dout[LOSS_OFF_ + b], sl[0] * (1.25f / 32768.f));

    // pack codes as (q_t0[c], q_t1[c]) pairs for the out-proj
    u64 q0 = f2pack(qa0.x, qb0.x), q1 = f2pack(qa0.y, qb0.y);
    u64 q2 = f2pack(qa0.z, qb0.z), q3 = f2pack(qa0.w, qb0.w);
    u64 q4 = f2pack(qa1.x, qb1.x), q5 = f2pack(qa1.y, qb1.y);
    u64 q6 = f2pack(qa1.z, qb1.z), q7 = f2pack(qa1.w, qb1.w);

    // out = W_out @ z_q + b_out  (STE forward value == z_q)
    float* outp = dout + (size_t)b * DIM_ * T_ + tl;
#pragma unroll 4
    for (int o = 0; o < DIM_; ++o) {
        const ulonglong2* wr = (const ulonglong2*)(g_Wout2 + o * 16);  // uniform splat
        ulonglong2 w0 = wr[0], w1 = wr[1], w2 = wr[2], w3 = wr[3];
        u64 acc = *(const u64*)(g_bout2 + o * 2);
        acc = f2fma(w0.x, q0, acc);
        acc = f2fma(w0.y, q1, acc);
        acc = f2fma(w1.x, q2, acc);
        acc = f2fma(w1.y, q3, acc);
        acc = f2fma(w2.x, q4, acc);
        acc = f2fma(w2.y, q5, acc);
        acc = f2fma(w3.x, q6, acc);
        acc = f2fma(w3.y, q7, acc);
        *(u64*)(outp + (size_t)o * T_) = acc;   // float2 store, coalesced 256B/warp
    }
}

// ---------------- launcher ----------------
extern "C" void kernel_launch(void* const* d_in, const int* in_sizes, int n_in,
                              void* d_out, int out_size)
{
    const float* z        = (const float*)d_in[0];
    const float* v_in     = (const float*)d_in[1];
    const float* g_in     = (const float*)d_in[2];
    const float* b_in     = (const float*)d_in[3];
    const float* codebook = (const float*)d_in[4];
    const float* v_out    = (const float*)d_in[5];
    const float* g_out    = (const float*)d_in[6];
    const float* b_out    = (const float*)d_in[7];
    float* out = (float*)d_out;

    prep_kernel<<<22, 256>>>(v_in, g_in, codebook, v_out, g_out, b_out, out);
    ze_kernel<<<BT_ / 256, 256>>>(z, b_in);
    vq_kernel<<<(BT_ / 2) / 128, 128>>>(codebook, out);
}

// round 2
// speedup vs baseline: 4.2277x; 4.2277x over previous
#include <cuda_runtime.h>

typedef unsigned long long u64;

#define B_    8
#define DIM_  1024
#define T_    4096
#define CB_   4096
#define CD_   8
#define BT_   (B_*T_)
#define NSL_  8
#define SLICE_ (CB_/NSL_)   // 512

static const size_t IDX_OFF_  = (size_t)B_ * DIM_ * T_;          // 33554432
static const size_t LOSS_OFF_ = (size_t)B_ * DIM_ * T_ + BT_;    // 33587200

// ---------------- device scratch (no allocations allowed) ----------------
__device__ float g_cn[CB_ * CD_];          // normalized codebook [j][c]
__device__ float g_Win[DIM_ * CD_];        // weight-normed in_proj, transposed [d][o]
__device__ float g_Wout2[DIM_ * 2 * CD_];  // weight-normed out_proj, splatted [o][c][2]
__device__ float g_bout2[DIM_ * 2];        // b_out splatted [o][2]
__device__ float g_ze[(size_t)BT_ * CD_];  // encodings z_e [t][c]  (1 MB)
__device__ int   g_idx[BT_];               // argmax indices
__device__ float g_qp[(size_t)BT_ * CD_];  // gathered codes, pair-interleaved [tp][c][2]

// ---------------- f32x2 helpers (FFMA2 only reachable via PTX) ----------------
__device__ __forceinline__ u64 f2mul(u64 a, u64 b) {
    u64 r; asm("mul.rn.f32x2 %0, %1, %2;" : "=l"(r) : "l"(a), "l"(b)); return r;
}
__device__ __forceinline__ u64 f2fma(u64 a, u64 b, u64 c) {
    u64 r; asm("fma.rn.f32x2 %0, %1, %2, %3;" : "=l"(r) : "l"(a), "l"(b), "l"(c)); return r;
}
__device__ __forceinline__ float2 f2unpack(u64 a) {
    float x, y; asm("mov.b64 {%0, %1}, %2;" : "=f"(x), "=f"(y) : "l"(a));
    return make_float2(x, y);
}

// ---------------- prep: weight-norm scales, normalized codebook, splats ----------------
__global__ void __launch_bounds__(256) prep_kernel(
    const float* __restrict__ v_in, const float* __restrict__ g_in,
    const float* __restrict__ codebook,
    const float* __restrict__ v_out, const float* __restrict__ g_out,
    const float* __restrict__ b_out, float* __restrict__ dout)
{
    const int r = blockIdx.x * 256 + threadIdx.x;
    if (r < CB_) {
        float v[CD_]; float s = 0.f;
#pragma unroll
        for (int c = 0; c < CD_; ++c) { v[c] = codebook[(size_t)r * CD_ + c]; s += v[c] * v[c]; }
        float n = fmaxf(sqrtf(s), 1e-12f);
#pragma unroll
        for (int c = 0; c < CD_; ++c) g_cn[(size_t)r * CD_ + c] = v[c] / n;
    } else if (r < CB_ + DIM_) {
        const int o = r - CB_;
        float v[CD_]; float s = 0.f;
#pragma unroll
        for (int c = 0; c < CD_; ++c) { v[c] = v_out[(size_t)o * CD_ + c]; s += v[c] * v[c]; }
        float sc = g_out[o] / sqrtf(s);
#pragma unroll
        for (int c = 0; c < CD_; ++c) {
            float w = v[c] * sc;
            g_Wout2[o * 16 + 2 * c]     = w;
            g_Wout2[o * 16 + 2 * c + 1] = w;
        }
        float bb = b_out[o];
        g_bout2[o * 2] = bb; g_bout2[o * 2 + 1] = bb;
    } else if (r < CB_ + DIM_ + CD_ * 32) {
        const int idx  = r - (CB_ + DIM_);
        const int w    = idx >> 5;
        const int lane = idx & 31;
        float s = 0.f;
        for (int d = lane; d < DIM_; d += 32) {
            float v = v_in[(size_t)w * DIM_ + d]; s += v * v;
        }
#pragma unroll
        for (int off = 16; off > 0; off >>= 1) s += __shfl_xor_sync(0xffffffffu, s, off);
        float sc = g_in[w] / sqrtf(s);
        for (int d = lane; d < DIM_; d += 32)
            g_Win[d * CD_ + w] = v_in[(size_t)w * DIM_ + d] * sc;
    } else if (r < CB_ + DIM_ + CD_ * 32 + B_) {
        dout[LOSS_OFF_ + (r - (CB_ + DIM_ + CD_ * 32))] = 0.f;
    }
}

// ---------------- K1: z_e = W_in @ z + b_in  (DIM split 4-way for occupancy) ----------------
__global__ void __launch_bounds__(256) ze_kernel(const float* __restrict__ z,
                                                 const float* __restrict__ b_in)
{
    const int tl = threadIdx.x & 63;       // timestep within block
    const int dc = threadIdx.x >> 6;       // 0..3 dim-chunk
    const int t  = blockIdx.x * 64 + tl;   // global timestep
    const int b  = t >> 12;
    const int tt = t & (T_ - 1);
    const float* zp = z + (size_t)b * DIM_ * T_ + tt + (size_t)(dc * 256) * T_;
    const float* wp = g_Win + dc * 256 * CD_;

    float a0 = 0.f, a1 = 0.f, a2 = 0.f, a3 = 0.f, a4 = 0.f, a5 = 0.f, a6 = 0.f, a7 = 0.f;
#pragma unroll 8
    for (int d = 0; d < 256; ++d) {
        float zv = __ldg(zp + (size_t)d * T_);          // coalesced, DRAM
        float4 w0 = *(const float4*)(wp + d * CD_);     // warp-uniform, L1
        float4 w1 = *(const float4*)(wp + d * CD_ + 4);
        a0 = fmaf(w0.x, zv, a0); a1 = fmaf(w0.y, zv, a1);
        a2 = fmaf(w0.z, zv, a2); a3 = fmaf(w0.w, zv, a3);
        a4 = fmaf(w1.x, zv, a4); a5 = fmaf(w1.y, zv, a5);
        a6 = fmaf(w1.z, zv, a6); a7 = fmaf(w1.w, zv, a7);
    }

    __shared__ float red[256 * 9];                      // pad 9 -> conflict-free
    float* my = red + threadIdx.x * 9;
    my[0] = a0; my[1] = a1; my[2] = a2; my[3] = a3;
    my[4] = a4; my[5] = a5; my[6] = a6; my[7] = a7;
    __syncthreads();

    if (threadIdx.x < 64) {
        const int tg = blockIdx.x * 64 + threadIdx.x;
        float acc[CD_];
#pragma unroll
        for (int c = 0; c < CD_; ++c) acc[c] = __ldg(b_in + c);
#pragma unroll
        for (int k = 0; k < 4; ++k) {
            const float* p = red + (k * 64 + threadIdx.x) * 9;
#pragma unroll
            for (int c = 0; c < CD_; ++c) acc[c] += p[c];
        }
        float4* o = (float4*)(g_ze + (size_t)tg * CD_);
        o[0] = make_float4(acc[0], acc[1], acc[2], acc[3]);
        o[1] = make_float4(acc[4], acc[5], acc[6], acc[7]);
    }
}

// ---------------- K2: argmax search, codebook split 8-way ----------------
// Block = 8 warps; warp w scans slice w for 32 consecutive timesteps.
// Codebook loads warp-uniform (L1 broadcast); z_e loads coalesced.
__global__ void __launch_bounds__(256) search_kernel()
{
    const int w    = threadIdx.x >> 5;     // slice 0..7
    const int lane = threadIdx.x & 31;
    const int t    = blockIdx.x * 32 + lane;

    const ulonglong2* zr = (const ulonglong2*)(g_ze + (size_t)t * CD_);
    ulonglong2 zA = zr[0], zB = zr[1];

    float best = -3.4e38f; int bj = 0;
    const ulonglong2* cr = (const ulonglong2*)g_cn + (size_t)w * SLICE_ * 2;
#pragma unroll 4
    for (int j = 0; j < SLICE_; ++j) {
        ulonglong2 c0 = cr[2 * j], c1 = cr[2 * j + 1];  // warp-uniform
        u64 d = f2mul(zA.x, c0.x);
        d = f2fma(zA.y, c0.y, d);
        d = f2fma(zB.x, c1.x, d);
        d = f2fma(zB.y, c1.y, d);
        float2 f = f2unpack(d);
        float dot = f.x + f.y;
        if (dot > best) { best = dot; bj = j; }          // strict > : lowest j on tie
    }
    bj += w * SLICE_;

    __shared__ float sv[NSL_][32];
    __shared__ int   si[NSL_][32];
    sv[w][lane] = best; si[w][lane] = bj;
    __syncthreads();

    if (threadIdx.x < 32) {
        float bv = sv[0][lane]; int bi = si[0][lane];
#pragma unroll
        for (int s = 1; s < NSL_; ++s) {
            float ov = sv[s][lane];
            if (ov > bv) { bv = ov; bi = si[s][lane]; }  // ascending s keeps lowest j
        }
        g_idx[t] = bi;
    }
}

// ---------------- K3: finalize — indices out, loss, gather + interleave codes ----------------
__global__ void __launch_bounds__(256) finalize_kernel(const float* __restrict__ codebook,
                                                       float* __restrict__ dout)
{
    const int t = blockIdx.x * 256 + threadIdx.x;
    const int b = t >> 12;
    const int idx = g_idx[t];

    dout[IDX_OFF_ + t] = (float)idx;

    float4 q0 = __ldg((const float4*)(codebook + (size_t)idx * CD_));
    float4 q1 = __ldg((const float4*)(codebook + (size_t)idx * CD_) + 1);
    const float4* er = (const float4*)(g_ze + (size_t)t * CD_);
    float4 e0 = er[0], e1 = er[1];

    float l = 0.f, d_;
    d_ = e0.x - q0.x; l += d_ * d_;  d_ = e0.y - q0.y; l += d_ * d_;
    d_ = e0.z - q0.z; l += d_ * d_;  d_ = e0.w - q0.w; l += d_ * d_;
    d_ = e1.x - q1.x; l += d_ * d_;  d_ = e1.y - q1.y; l += d_ * d_;
    d_ = e1.z - q1.z; l += d_ * d_;  d_ = e1.w - q1.w; l += d_ * d_;

    // pair-interleaved code store: g_qp[tp][c][2]
    float* qp = g_qp + (size_t)(t >> 1) * 16 + (t & 1);
    qp[0]  = q0.x; qp[2]  = q0.y; qp[4]  = q0.z; qp[6]  = q0.w;
    qp[8]  = q1.x; qp[10] = q1.y; qp[12] = q1.z; qp[14] = q1.w;

    __shared__ float sl[256];
    sl[threadIdx.x] = l;
    __syncthreads();
#pragma unroll
    for (int s = 128; s > 0; s >>= 1) {
        if (threadIdx.x < s) sl[threadIdx.x] += sl[threadIdx.x + s];
        __syncthreads();
    }
    if (threadIdx.x == 0)
        atomicAdd(&dout[LOSS_OFF_ + b], sl[0] * (1.25f / 32768.f));
}

// ---------------- K4: out-proj, DIM split 16-way (64 rows per thread) ----------------
__global__ void __launch_bounds__(256) outproj_kernel(float* __restrict__ dout)
{
    const int u  = blockIdx.x * 256 + threadIdx.x;
    const int tp = u & (BT_ / 2 - 1);      // t-pair id (low bits -> coalesced)
    const int oc = u >> 14;                // 0..15 dim chunk (warp-uniform)
    const int t0 = tp << 1;
    const int b  = t0 >> 12;
    const int tl = t0 & (T_ - 1);

    const ulonglong2* qr = (const ulonglong2*)(g_qp + (size_t)tp * 16);
    ulonglong2 qA = qr[0], qB = qr[1], qC = qr[2], qD = qr[3];

    float* outp = dout + (size_t)b * DIM_ * T_ + tl + (size_t)(oc * 64) * T_;
    const float* wbase = g_Wout2 + oc * 64 * 16;
    const float* bbase = g_bout2 + oc * 64 * 2;

#pragma unroll 4
    for (int o = 0; o < 64; ++o) {
        const ulonglong2* wr = (const ulonglong2*)(wbase + o * 16);   // warp-uniform
        ulonglong2 w0 = wr[0], w1 = wr[1], w2 = wr[2], w3 = wr[3];
        u64 acc = *(const u64*)(bbase + o * 2);
        acc = f2fma(w0.x, qA.x, acc);
        acc = f2fma(w0.y, qA.y, acc);
        acc = f2fma(w1.x, qB.x, acc);
        acc = f2fma(w1.y, qB.y, acc);
        acc = f2fma(w2.x, qC.x, acc);
        acc = f2fma(w2.y, qC.y, acc);
        acc = f2fma(w3.x, qD.x, acc);
        acc = f2fma(w3.y, qD.y, acc);
        *(u64*)(outp + (size_t)o * T_) = acc;   // float2 store, 256B/warp
    }
}

// ---------------- launcher ----------------
extern "C" void kernel_launch(void* const* d_in, const int* in_sizes, int n_in,
                              void* d_out, int out_size)
{
    const float* z        = (const float*)d_in[0];
    const float* v_in     = (const float*)d_in[1];
    const float* g_in     = (const float*)d_in[2];
    const float* b_in     = (const float*)d_in[3];
    const float* codebook = (const float*)d_in[4];
    const float* v_out    = (const float*)d_in[5];
    const float* g_out    = (const float*)d_in[6];
    const float* b_out    = (const float*)d_in[7];
    float* out = (float*)d_out;

    prep_kernel<<<22, 256>>>(v_in, g_in, codebook, v_out, g_out, b_out, out);
    ze_kernel<<<BT_ / 64, 256>>>(z, b_in);
    search_kernel<<<BT_ / 32, 256>>>();
    finalize_kernel<<<BT_ / 256, 256>>>(codebook, out);
    outproj_kernel<<<(BT_ / 2) * 16 / 256, 256>>>(out);
}